// round 4
// baseline (speedup 1.0000x reference)
#include <cuda_runtime.h>

#define PI_F 3.14159265358979323846f

constexpr int HW      = 81;
constexpr int NG      = 4;
constexpr long long NX = 512LL * 512LL * 81LL;   // 21,233,664 elements of x
constexpr int N4      = (int)(NX / 4);            // 5,308,416 float4 chunks
constexpr int THREADS = 256;
constexpr int BLOCKS  = 5184;                     // 81*64: stride divisible by 81,
                                                  // 34.1 CTAs/SM -> ~3% tail imbalance
constexpr int TOTAL_T = BLOCKS * THREADS;         // 1,327,104
constexpr int ITERS   = N4 / TOTAL_T;             // 4 exactly

__global__ __launch_bounds__(THREADS)
void gabor_mul_kernel(const float* __restrict__ x,
                      const float* __restrict__ theta,
                      const float* __restrict__ lam,
                      float* __restrict__ out)
{
    // --- Build the 4x81 Gabor filter table in shared memory (tiny) ---
    __shared__ float filt[NG * HW];
    for (int i = threadIdx.x; i < NG * HW; i += THREADS) {
        int g  = i / HW;
        int hw = i % HW;
        float fy = (float)(hw / 9) - 4.0f;   // ys = arange(9) - 4
        float fx = (float)(hw % 9) - 4.0f;   // xs = arange(9) - 4
        float th = theta[g];
        float l  = lam[g];
        float s, c;
        sincosf(th, &s, &c);
        float xr = fx * c + fy * s;
        float yr = -fx * s + fy * c;
        float env = expf(-(xr * xr + yr * yr) * (0.5f / (PI_F * PI_F))); // sigma = pi
        filt[i] = env * cosf(2.0f * PI_F * xr * l);
    }
    __syncthreads();

    // --- Hoist this thread's 16 filter values into registers ---
    // Iteration stride TOTAL_T*4 = 5,308,416 elements is divisible by 81,
    // so each lane's hw phase is invariant across all 4 iterations.
    int t0  = blockIdx.x * THREADS + threadIdx.x;
    int hw0 = (int)(((long long)t0 * 4) % HW);

    float f[NG][4];
#pragma unroll
    for (int g = 0; g < NG; g++) {
        int h = hw0;
#pragma unroll
        for (int k = 0; k < 4; k++) {
            f[g][k] = filt[g * HW + h];
            h++;
            if (h == HW) h = 0;
        }
    }

    const float4* __restrict__ x4 = (const float4*)x;
    float4* __restrict__ og[NG];
#pragma unroll
    for (int g = 0; g < NG; g++) og[g] = (float4*)(out + (size_t)g * NX);

    // Entire per-thread workload: 4 independent LDG.128 batched up front
    // (MLP=4), then 16 streaming STG.128. No loop-carry at all.
    float4 v[ITERS];
#pragma unroll
    for (int j = 0; j < ITERS; j++)
        v[j] = x4[t0 + j * TOTAL_T];

#pragma unroll
    for (int j = 0; j < ITERS; j++) {
        int idx = t0 + j * TOTAL_T;
#pragma unroll
        for (int g = 0; g < NG; g++) {
            float4 o;
            o.x = f[g][0] * v[j].x;
            o.y = f[g][1] * v[j].y;
            o.z = f[g][2] * v[j].z;
            o.w = f[g][3] * v[j].w;
            __stcs(&og[g][idx], o);
        }
    }
}

extern "C" void kernel_launch(void* const* d_in, const int* in_sizes, int n_in,
                              void* d_out, int out_size)
{
    const float* x     = (const float*)d_in[0];
    const float* theta = (const float*)d_in[1];
    const float* lam   = (const float*)d_in[2];
    float* out         = (float*)d_out;

    gabor_mul_kernel<<<BLOCKS, THREADS>>>(x, theta, lam, out);
}

// round 5
// speedup vs baseline: 1.0959x; 1.0959x over previous
#include <cuda_runtime.h>

#define PI_F 3.14159265358979323846f

constexpr int HW      = 81;
constexpr int NG      = 4;
constexpr long long NX = 512LL * 512LL * 81LL;   // 21,233,664 elements of x
constexpr int N4      = (int)(NX / 4);            // 5,308,416 float4 chunks
constexpr int THREADS = 256;
constexpr int BLOCKS  = 5184;                     // 81*64: stride divisible by 81,
                                                  // ~34 CTAs/SM -> ~3% tail imbalance
constexpr int TOTAL_T = BLOCKS * THREADS;         // 1,327,104
constexpr int ITERS   = N4 / TOTAL_T;             // 4 exactly

// Precomputed 4x81 Gabor table (1.3 KB), built once per launch by a tiny kernel.
__device__ float g_filt[NG * HW];

__global__ void build_filters(const float* __restrict__ theta,
                              const float* __restrict__ lam)
{
    int i = threadIdx.x;
    if (i >= NG * HW) return;
    int g  = i / HW;
    int hw = i % HW;
    float fy = (float)(hw / 9) - 4.0f;   // ys = arange(9) - 4
    float fx = (float)(hw % 9) - 4.0f;   // xs = arange(9) - 4
    float th = theta[g];
    float l  = lam[g];
    float s, c;
    sincosf(th, &s, &c);
    float xr = fx * c + fy * s;
    float yr = -fx * s + fy * c;
    float env = expf(-(xr * xr + yr * yr) * (0.5f / (PI_F * PI_F))); // sigma = pi
    g_filt[i] = env * cosf(2.0f * PI_F * xr * l);
}

__global__ __launch_bounds__(THREADS)
void gabor_mul_kernel(const float* __restrict__ x,
                      float* __restrict__ out)
{
    // Cheap prologue: 16 scalar loads from the 1.3KB resident table.
    // Iteration stride TOTAL_T*4 = 5,308,416 elements is divisible by 81,
    // so each lane's hw phase is invariant across all 4 iterations.
    int t0  = blockIdx.x * THREADS + threadIdx.x;
    int hw0 = (t0 * 4) % HW;

    float f[NG][4];
#pragma unroll
    for (int g = 0; g < NG; g++) {
        int h = hw0;
#pragma unroll
        for (int k = 0; k < 4; k++) {
            f[g][k] = g_filt[g * HW + h];
            h++;
            if (h == HW) h = 0;
        }
    }

    const float4* __restrict__ x4 = (const float4*)x;
    float4* __restrict__ og[NG];
#pragma unroll
    for (int g = 0; g < NG; g++) og[g] = (float4*)(out + (size_t)g * NX);

    // Entire per-thread workload: 4 independent LDG.128 batched up front
    // (MLP=4), then 16 streaming STG.128. x uses default caching (L2-resident
    // across replays); stores are evict-first so they don't evict x.
    float4 v[ITERS];
#pragma unroll
    for (int j = 0; j < ITERS; j++)
        v[j] = x4[t0 + j * TOTAL_T];

#pragma unroll
    for (int j = 0; j < ITERS; j++) {
        int idx = t0 + j * TOTAL_T;
#pragma unroll
        for (int g = 0; g < NG; g++) {
            float4 o;
            o.x = f[g][0] * v[j].x;
            o.y = f[g][1] * v[j].y;
            o.z = f[g][2] * v[j].z;
            o.w = f[g][3] * v[j].w;
            __stcs(&og[g][idx], o);
        }
    }
}

extern "C" void kernel_launch(void* const* d_in, const int* in_sizes, int n_in,
                              void* d_out, int out_size)
{
    const float* x     = (const float*)d_in[0];
    const float* theta = (const float*)d_in[1];
    const float* lam   = (const float*)d_in[2];
    float* out         = (float*)d_out;

    build_filters<<<1, NG * HW>>>(theta, lam);
    gabor_mul_kernel<<<BLOCKS, THREADS>>>(x, out);
}